// round 12
// baseline (speedup 1.0000x reference)
#include <cuda_runtime.h>
#include <cuda_fp16.h>
#include <math.h>
#include <stdint.h>

#define TT 2048
#define HH 2048
#define II 1024
#define EE 32
#define TOPK 4
#define NROUTED (TT*TOPK)
#define NPAIRS  (NROUTED + TT)

// GEMM tiling: BM=128, BN=128, BK=64, 256 thr, 2 CTA/SM, persistent
#define BM 128
#define BN 128
#define BK 64
#define NTHR 256
#define ROWB 144
#define OFF_A 0
#define OFF_B 18432
#define BUFSZ 36864
#define SMEM_DYN (2*BUFSZ)
#define NCTA 296
#define MAXTILES 160

// ---------------- device scratch ----------------
__device__ int   g_counts[EE];
__device__ int   g_cursor[EE];
__device__ int   g_offsets[EE];
__device__ int   g_topk_idx[NROUTED];
__device__ float g_topk_w[NROUTED];
__device__ int   g_pair_token[NROUTED];
__device__ int   g_pair_pos[NROUTED];
__device__ int   g_tg[MAXTILES];
__device__ int   g_tm[MAXTILES];
__device__ int   g_ntile;
__device__ int   g_workA;
__device__ int   g_workB;
__device__ __half g_xh[(size_t)TT*HH];
__device__ float g_C1[(size_t)NPAIRS*II];
__device__ float g_C3[(size_t)NPAIRS*II];
__device__ __half g_acth[(size_t)NPAIRS*II];
__device__ float g_pairout[(size_t)NPAIRS*HH];

// ---------------- helpers ----------------
__device__ __forceinline__ void cvt2h(unsigned &r, float hi_elem, float lo_elem) {
    asm("cvt.rn.f16x2.f32 %0, %1, %2;" : "=r"(r) : "f"(hi_elem), "f"(lo_elem));
}
__device__ __forceinline__ void ldsm4(unsigned &r0, unsigned &r1, unsigned &r2, unsigned &r3,
                                      unsigned addr) {
    asm volatile("ldmatrix.sync.aligned.m8n8.x4.shared.b16 {%0,%1,%2,%3}, [%4];"
                 : "=r"(r0), "=r"(r1), "=r"(r2), "=r"(r3) : "r"(addr));
}
__device__ __forceinline__ void mma16816(float* c, const unsigned* a, unsigned b0, unsigned b1) {
    asm volatile("mma.sync.aligned.m16n8k16.row.col.f32.f16.f16.f32 "
                 "{%0,%1,%2,%3}, {%4,%5,%6,%7}, {%8,%9}, {%0,%1,%2,%3};"
                 : "+f"(c[0]), "+f"(c[1]), "+f"(c[2]), "+f"(c[3])
                 : "r"(a[0]), "r"(a[1]), "r"(a[2]), "r"(a[3]), "r"(b0), "r"(b1));
}
__device__ __forceinline__ void cp16(unsigned dst, const void* src) {
    asm volatile("cp.async.cg.shared.global [%0], [%1], 16;" :: "r"(dst), "l"(src));
}

// ---------------- small kernels ----------------
__global__ void zero_kernel() {
    int i = threadIdx.x;
    if (i < EE) { g_counts[i] = 0; g_cursor[i] = 0; }
    if (i == 0) { g_workA = 0; g_workB = 0; }
}
__global__ void offsets_kernel() {
    if (threadIdx.x == 0) {
        int s = 0;
        for (int e = 0; e < EE; ++e) { g_offsets[e] = s; s += g_counts[e]; }
        int nt = 0;
        for (int e = 0; e < EE; ++e)
            for (int m = 0; m * BM < g_counts[e]; ++m) { g_tg[nt] = e; g_tm[nt] = m; ++nt; }
        for (int m = 0; m < TT / BM; ++m) { g_tg[nt] = EE; g_tm[nt] = m; ++nt; }
        g_ntile = nt;
    }
}
__global__ void scatter_kernel() {
    int t = blockIdx.x * blockDim.x + threadIdx.x;
    if (t >= TT) return;
    #pragma unroll
    for (int j = 0; j < TOPK; ++j) {
        int e = g_topk_idx[t*TOPK + j];
        int pos = g_offsets[e] + atomicAdd(&g_cursor[e], 1);
        g_pair_token[pos] = t;
        g_pair_pos[t*TOPK + j] = pos;
    }
}
__global__ __launch_bounds__(256) void act_kernel() {
    size_t i4 = (size_t)blockIdx.x * 256 + threadIdx.x;
    float4 a = ((const float4*)g_C1)[i4];
    float4 b = ((const float4*)g_C3)[i4];
    float v0 = a.x / (1.f + expf(-a.x)) * b.x;
    float v1 = a.y / (1.f + expf(-a.y)) * b.y;
    float v2 = a.z / (1.f + expf(-a.z)) * b.z;
    float v3 = a.w / (1.f + expf(-a.w)) * b.w;
    unsigned h01, h23;
    cvt2h(h01, v1, v0);
    cvt2h(h23, v3, v2);
    ((uint2*)g_acth)[i4] = make_uint2(h01, h23);
}

// ---------------- gate + routing + x->fp16 (fused) ----------------
__global__ __launch_bounds__(256) void gate_kernel(
        const float* __restrict__ x, const float* __restrict__ gw,
        const float* __restrict__ bias)
{
    __shared__ float xs[4][HH];
    __shared__ float logits_s[4][EE];
    __shared__ float bias_s[EE];
    int tid = threadIdx.x;
    int t0  = blockIdx.x * 4;
    const float4* xg  = (const float4*)(x + (size_t)t0 * HH);
    float4*       xs4 = (float4*)&xs[0][0];
    #pragma unroll
    for (int i = 0; i < 8; ++i) xs4[tid + i*256] = xg[tid + i*256];
    if (tid < EE) bias_s[tid] = bias[tid];
    __syncthreads();

    // fused convx: write fp16 copy of these 4 rows
    {
        uint2* dst = (uint2*)(g_xh + (size_t)t0 * HH);
        #pragma unroll
        for (int i = 0; i < 8; ++i) {
            float4 v = xs4[tid + i*256];
            unsigned h01, h23;
            cvt2h(h01, v.y, v.x);
            cvt2h(h23, v.w, v.z);
            dst[tid + i*256] = make_uint2(h01, h23);
        }
    }

    int warp = tid >> 5, lane = tid & 31;
    #pragma unroll
    for (int ei = 0; ei < 4; ++ei) {
        int e = warp*4 + ei;
        const float* gr = gw + (size_t)e * HH;
        float a0=0.f, a1=0.f, a2=0.f, a3=0.f;
        for (int h = lane; h < HH; h += 32) {
            float g = gr[h];
            a0 = fmaf(g, xs[0][h], a0); a1 = fmaf(g, xs[1][h], a1);
            a2 = fmaf(g, xs[2][h], a2); a3 = fmaf(g, xs[3][h], a3);
        }
        #pragma unroll
        for (int off = 16; off; off >>= 1) {
            a0 += __shfl_xor_sync(0xffffffffu, a0, off);
            a1 += __shfl_xor_sync(0xffffffffu, a1, off);
            a2 += __shfl_xor_sync(0xffffffffu, a2, off);
            a3 += __shfl_xor_sync(0xffffffffu, a3, off);
        }
        if (lane == 0) {
            logits_s[0][e] = a0; logits_s[1][e] = a1;
            logits_s[2][e] = a2; logits_s[3][e] = a3;
        }
    }
    __syncthreads();
    if (warp < 4) {
        int t = t0 + warp;
        float logit = logits_s[warp][lane];
        float s   = 1.f / (1.f + expf(-logit));
        float sfc = s + bias_s[lane];
        float m1 = sfc, m2 = -INFINITY;
        #pragma unroll
        for (int off = 4; off >= 1; off >>= 1) {
            float o1 = __shfl_xor_sync(0xffffffffu, m1, off);
            float o2 = __shfl_xor_sync(0xffffffffu, m2, off);
            float hi = fmaxf(m1, o1);
            float lo = fmaxf(fminf(m1, o1), fmaxf(m2, o2));
            m1 = hi; m2 = lo;
        }
        float gs = m1 + m2;
        float gv[4];
        gv[0] = __shfl_sync(0xffffffffu, gs, 0);
        gv[1] = __shfl_sync(0xffffffffu, gs, 8);
        gv[2] = __shfl_sync(0xffffffffu, gs, 16);
        gv[3] = __shfl_sync(0xffffffffu, gs, 24);
        int b1 = 0; float v1 = gv[0];
        #pragma unroll
        for (int gg = 1; gg < 4; ++gg) if (gv[gg] > v1) { v1 = gv[gg]; b1 = gg; }
        int b2 = -1; float v2 = -INFINITY;
        #pragma unroll
        for (int gg = 0; gg < 4; ++gg) {
            if (gg == b1) continue;
            if (gv[gg] > v2) { v2 = gv[gg]; b2 = gg; }
        }
        int mygrp = lane >> 3;
        float val = (mygrp == b1 || mygrp == b2) ? sfc : 0.0f;
        int sel_i[TOPK]; float sel_w[TOPK];
        float cur = val;
        #pragma unroll
        for (int j = 0; j < TOPK; ++j) {
            float bv = cur; int bi = lane;
            #pragma unroll
            for (int off = 16; off >= 1; off >>= 1) {
                float ov = __shfl_xor_sync(0xffffffffu, bv, off);
                int   oi = __shfl_xor_sync(0xffffffffu, bi, off);
                if (ov > bv || (ov == bv && oi < bi)) { bv = ov; bi = oi; }
            }
            sel_i[j] = bi;
            sel_w[j] = __shfl_sync(0xffffffffu, s, bi);
            if (lane == bi) cur = -INFINITY;
        }
        if (lane == 0) {
            float sum = sel_w[0] + sel_w[1] + sel_w[2] + sel_w[3];
            float scale = 2.5f / (sum + 1e-20f);
            #pragma unroll
            for (int j = 0; j < TOPK; ++j) {
                g_topk_idx[t*TOPK + j] = sel_i[j];
                g_topk_w[t*TOPK + j]   = sel_w[j] * scale;
                atomicAdd(&g_counts[sel_i[j]], 1);
            }
        }
    }
}

// ---------------- persistent grouped fp16 GEMM ----------------
__global__ void __launch_bounds__(NTHR, 2) gemm_kernel(
    const __half* __restrict__ A, int lda,
    const float* __restrict__ Wra, const float* __restrict__ Wsa,
    const float* __restrict__ Wrb, const float* __restrict__ Wsb,
    int Kdim, int ybnd, float* __restrict__ Ca, float* __restrict__ Cb,
    int ldc, int gather, int* __restrict__ work)
{
    extern __shared__ char sm[];
    __shared__ int s_toks[BM];
    __shared__ int s_item;
    const unsigned smb = (unsigned)__cvta_generic_to_shared(sm);
    const int tid = threadIdx.x;
    const int warp = tid >> 5, lane = tid & 31;
    const int wm = (warp & 1) * 64;
    const int wn = (warp >> 1) * 32;
    const int l15 = lane & 15, lh = lane >> 4;
    const size_t wsz = (size_t)II * HH;
    const int S = Kdim / BK;

    for (;;) {
        if (tid == 0) s_item = atomicAdd(work, 1);
        __syncthreads();
        const int item = s_item;
        const int ntile = g_ntile;
        if (item >= ntile * 16) break;
        const int tile = item >> 4;
        const int y = item & 15;
        const int g = g_tg[tile];
        const int mtile = g_tm[tile];

        int m_count, base_pos;
        if (g < EE) { m_count = g_counts[g]; base_pos = g_offsets[g]; }
        else        { m_count = TT;          base_pos = NROUTED; }
        const int rows = min(BM, m_count - mtile * BM);

        const float* W;
        float* C;
        int n0;
        if (y < ybnd) {
            W = (g < EE) ? (Wra + (size_t)g * wsz) : Wsa;
            C = Ca; n0 = y * BN;
        } else {
            W = (g < EE) ? (Wrb + (size_t)g * wsz) : Wsb;
            C = Cb; n0 = (y - ybnd) * BN;
        }

        if (tid < BM) {
            int r = min(tid, rows - 1);
            int pos = base_pos + mtile*BM + r;
            s_toks[tid] = gather ? ((g < EE) ? g_pair_token[pos] : (mtile*BM + r)) : pos;
        }
        __syncthreads();

        float acc[4][4][4];
        #pragma unroll
        for (int i = 0; i < 4; ++i)
            #pragma unroll
            for (int j = 0; j < 4; ++j)
                #pragma unroll
                for (int q = 0; q < 4; ++q) acc[i][j][q] = 0.f;

        #define LOAD_A(dstb, k0) do {                                            \
            _Pragma("unroll")                                                    \
            for (int t = 0; t < 4; ++t) {                                        \
                int c = tid + t*NTHR;                                            \
                int row = c >> 3, ch = c & 7;                                    \
                const __half* srcp = A + (size_t)s_toks[row]*lda + (k0) + ch*8;  \
                cp16((dstb) + OFF_A + row*ROWB + ch*16, srcp);                   \
            }                                                                    \
        } while(0)
        #define LDG_B(bv, k0, h) do {                                            \
            _Pragma("unroll")                                                    \
            for (int t = 0; t < 4; ++t) {                                        \
                int c = tid + t*NTHR;                                            \
                int row = c >> 3, f4 = c & 7;                                    \
                (bv)[t] = *(const float4*)(W + (size_t)(n0+row)*Kdim + (k0) + (h)*32 + f4*4); \
            }                                                                    \
        } while(0)
        #define STS_B(bv, dstg, h) do {                                          \
            _Pragma("unroll")                                                    \
            for (int t = 0; t < 4; ++t) {                                        \
                int c = tid + t*NTHR;                                            \
                int row = c >> 3, f4 = c & 7;                                    \
                unsigned h01, h23;                                               \
                cvt2h(h01, (bv)[t].y, (bv)[t].x);                                \
                cvt2h(h23, (bv)[t].w, (bv)[t].z);                                \
                *(uint2*)((dstg) + OFF_B + row*ROWB + (h)*64 + f4*8) = make_uint2(h01, h23); \
            }                                                                    \
        } while(0)
        #define COMPUTE_HALF(cb, kk0) do {                                       \
            _Pragma("unroll")                                                    \
            for (int kk = (kk0); kk < (kk0) + 32; kk += 16) {                    \
                unsigned bh[2][4];                                               \
                _Pragma("unroll")                                                \
                for (int nf2 = 0; nf2 < 2; ++nf2) {                              \
                    unsigned addr = (cb) + OFF_B + (wn + nf2*16 + l15)*ROWB + (kk + lh*8)*2; \
                    ldsm4(bh[nf2][0], bh[nf2][1], bh[nf2][2], bh[nf2][3], addr); \
                }                                                                \
                _Pragma("unroll")                                                \
                for (int mf = 0; mf < 4; ++mf) {                                 \
                    unsigned ah[4];                                              \
                    unsigned addr = (cb) + OFF_A + (wm + mf*16 + l15)*ROWB + (kk + lh*8)*2; \
                    ldsm4(ah[0], ah[1], ah[2], ah[3], addr);                     \
                    _Pragma("unroll")                                            \
                    for (int nf2 = 0; nf2 < 2; ++nf2) {                          \
                        _Pragma("unroll")                                        \
                        for (int u = 0; u < 2; ++u)                              \
                            mma16816(acc[mf][nf2*2 + u], ah, bh[nf2][u], bh[nf2][2 + u]); \
                    }                                                            \
                }                                                                \
            }                                                                    \
        } while(0)

        {
            float4 bv[4];
            LOAD_A(smb, 0);
            asm volatile("cp.async.commit_group;");
            LDG_B(bv, 0, 0);
            STS_B(bv, sm, 0);
            LDG_B(bv, 0, 1);
            STS_B(bv, sm, 1);
            asm volatile("cp.async.wait_group 0;" ::: "memory");
            __syncthreads();
        }

        int buf = 0;
        for (int s = 0; s < S; ++s) {
            const unsigned cb = smb + buf * BUFSZ;
            const unsigned nb = smb + (buf ^ 1) * BUFSZ;
            char* nbg = sm + (buf ^ 1) * BUFSZ;
            const int k0n = (s + 1) * BK;
            const bool more = (s + 1 < S);
            float4 bv[4];

            if (more) {
                LDG_B(bv, k0n, 0);
                LOAD_A(nb, k0n);
                asm volatile("cp.async.commit_group;");
            }
            COMPUTE_HALF(cb, 0);
            if (more) {
                STS_B(bv, nbg, 0);
                LDG_B(bv, k0n, 1);
            }
            COMPUTE_HALF(cb, 32);
            if (more) {
                STS_B(bv, nbg, 1);
                asm volatile("cp.async.wait_group 0;" ::: "memory");
            }
            __syncthreads();
            buf ^= 1;
        }

        const int gq = lane >> 2, tau = lane & 3;
        #pragma unroll
        for (int mf = 0; mf < 4; ++mf) {
            #pragma unroll
            for (int nf = 0; nf < 4; ++nf) {
                int col = n0 + wn + nf*8 + tau*2;
                int r0 = wm + mf*16 + gq;
                int r1 = r0 + 8;
                if (r0 < rows) {
                    float* d = C + (size_t)(base_pos + mtile*BM + r0) * ldc + col;
                    d[0] = acc[mf][nf][0]; d[1] = acc[mf][nf][1];
                }
                if (r1 < rows) {
                    float* d = C + (size_t)(base_pos + mtile*BM + r1) * ldc + col;
                    d[0] = acc[mf][nf][2]; d[1] = acc[mf][nf][3];
                }
            }
        }
        __syncthreads();
    }
}

// ---------------- combine ----------------
__global__ __launch_bounds__(256) void combine_kernel(float* __restrict__ out)
{
    const int t = blockIdx.x;
    const int tid = threadIdx.x;
    __shared__ float w[TOPK];
    __shared__ int   pos[TOPK];
    if (tid < TOPK) {
        w[tid]   = g_topk_w[t*TOPK + tid];
        pos[tid] = g_pair_pos[t*TOPK + tid];
    }
    __syncthreads();
    const float4* sh = (const float4*)(g_pairout + (size_t)(NROUTED + t) * HH);
    const float4* p0 = (const float4*)(g_pairout + (size_t)pos[0] * HH);
    const float4* p1 = (const float4*)(g_pairout + (size_t)pos[1] * HH);
    const float4* p2 = (const float4*)(g_pairout + (size_t)pos[2] * HH);
    const float4* p3 = (const float4*)(g_pairout + (size_t)pos[3] * HH);
    float4* o = (float4*)(out + (size_t)t * HH);
    const float w0=w[0], w1=w[1], w2=w[2], w3=w[3];
    #pragma unroll
    for (int it = 0; it < HH/4/256; ++it) {
        int i = tid + it*256;
        float4 acc = sh[i];
        float4 v0 = p0[i], v1 = p1[i], v2 = p2[i], v3 = p3[i];
        acc.x += w0*v0.x + w1*v1.x + w2*v2.x + w3*v3.x;
        acc.y += w0*v0.y + w1*v1.y + w2*v2.y + w3*v3.y;
        acc.z += w0*v0.z + w1*v1.z + w2*v2.z + w3*v3.z;
        acc.w += w0*v0.w + w1*v1.w + w2*v2.w + w3*v3.w;
        o[i] = acc;
    }
}

// ---------------- launch ----------------
extern "C" void kernel_launch(void* const* d_in, const int* in_sizes, int n_in,
                              void* d_out, int out_size)
{
    const float* x    = (const float*)d_in[0];
    const float* gw   = (const float*)d_in[1];
    const float* bias = (const float*)d_in[2];
    const float* w1   = (const float*)d_in[3];
    const float* w3   = (const float*)d_in[4];
    const float* w2   = (const float*)d_in[5];
    const float* ws1  = (const float*)d_in[6];
    const float* ws3  = (const float*)d_in[7];
    const float* ws2  = (const float*)d_in[8];
    float* out = (float*)d_out;

    cudaFuncSetAttribute(gemm_kernel, cudaFuncAttributeMaxDynamicSharedMemorySize, SMEM_DYN);

    zero_kernel<<<1, 64>>>();
    gate_kernel<<<TT/4, 256>>>(x, gw, bias);
    offsets_kernel<<<1, 32>>>();
    scatter_kernel<<<TT/256, 256>>>();

    __half *xh, *ah;
    cudaGetSymbolAddress((void**)&xh, g_xh);
    cudaGetSymbolAddress((void**)&ah, g_acth);
    float *c1, *c3, *po;
    cudaGetSymbolAddress((void**)&c1, g_C1);
    cudaGetSymbolAddress((void**)&c3, g_C3);
    cudaGetSymbolAddress((void**)&po, g_pairout);
    int *wA, *wB;
    cudaGetSymbolAddress((void**)&wA, g_workA);
    cudaGetSymbolAddress((void**)&wB, g_workB);

    // phase A: C1 = X@W1^T (y<8), C3 = X@W3^T (y>=8); K=HH
    gemm_kernel<<<NCTA, NTHR, SMEM_DYN>>>(
        xh, HH, w1, ws1, w3, ws3, HH, 8, c1, c3, II, 1, wA);
    act_kernel<<<(int)((size_t)NPAIRS*II/4/256), 256>>>();
    // phase B: pairout = act@W2^T; K=II
    gemm_kernel<<<NCTA, NTHR, SMEM_DYN>>>(
        ah, II, w2, ws2, w2, ws2, II, 16, po, po, HH, 0, wB);
    combine_kernel<<<TT, 256>>>(out);
}